// round 2
// baseline (speedup 1.0000x reference)
#include <cuda_runtime.h>
#include <cuda_bf16.h>
#include <math.h>

#define NN 50000
#define EE 800000
#define HH 64

// ---------------- scratch (device globals; no runtime alloc) ----------------
__device__ float g_emb[(size_t)NN * 256];   // [x | h1 | h2 | h3]
__device__ float g_t[(size_t)NN * 64];      // pre-mlp intermediate
__device__ float g_yr[(size_t)NN * 128];    // per-layer [y | r]
__device__ float g_Wp[192 * 128];           // packed gated [wl | wr]
__device__ int   g_cnt[NN];
__device__ int   g_rowptr[NN];
__device__ int   g_cursor[NN];
__device__ int   g_csr_src[EE];
__device__ float g_invdeg[NN];
__device__ float g_s[256];

// ---------------- setup kernels ----------------
__global__ void zero_kernel() {
    int i = blockIdx.x * blockDim.x + threadIdx.x;
    if (i < NN) g_cnt[i] = 0;
    if (i < 256) g_s[i] = 0.f;
}

__global__ void hist_kernel(const int* __restrict__ ei) {
    int e = blockIdx.x * blockDim.x + threadIdx.x;
    if (e < EE) atomicAdd(&g_cnt[ei[EE + e]], 1);
}

// single-block scan over 50000 counts -> rowptr/cursor/invdeg
__global__ void scan_kernel() {
    __shared__ int partial[1024];
    const int CH = (NN + 1023) / 1024;  // 49
    int tid = threadIdx.x;
    int start = tid * CH;
    int sum = 0;
    for (int i = 0; i < CH; i++) {
        int idx = start + i;
        if (idx < NN) sum += g_cnt[idx];
    }
    partial[tid] = sum;
    __syncthreads();
    for (int off = 1; off < 1024; off <<= 1) {
        int add = (tid >= off) ? partial[tid - off] : 0;
        __syncthreads();
        partial[tid] += add;
        __syncthreads();
    }
    int base = (tid == 0) ? 0 : partial[tid - 1];
    for (int i = 0; i < CH; i++) {
        int idx = start + i;
        if (idx < NN) {
            int c = g_cnt[idx];
            g_rowptr[idx] = base;
            g_cursor[idx] = base;
            g_invdeg[idx] = 1.0f / (float)(c > 1 ? c : 1);
            base += c;
        }
    }
}

__global__ void scatter_kernel(const int* __restrict__ ei) {
    int e = blockIdx.x * blockDim.x + threadIdx.x;
    if (e < EE) {
        int dst = ei[EE + e];
        int pos = atomicAdd(&g_cursor[dst], 1);
        g_csr_src[pos] = ei[e];
    }
}

// ---------------- SGEMM: C[M,NC] = act(A[M,K] @ W[K,NC] + bias) ----------------
template <int BN>
__global__ void sgemm_kernel(const float* __restrict__ A, int lda, int K,
                             const float* __restrict__ W, int NC,
                             float* __restrict__ C, int ldc, int M,
                             const float* __restrict__ bias, int act) {
    constexpr int BM = 128, BK = 8, TM = 8;
    constexpr int TCOLS = 16;
    constexpr int TN = BN / TCOLS;
    __shared__ float As[BK][BM];
    __shared__ float Bs[BK][BN];
    const int bm = blockIdx.y * BM;
    const int bn = blockIdx.x * BN;
    const int tid = threadIdx.x;
    const int tc = tid % TCOLS;
    const int tr = tid / TCOLS;  // 0..15

    float acc[TM][TN];
#pragma unroll
    for (int i = 0; i < TM; i++)
#pragma unroll
        for (int j = 0; j < TN; j++) acc[i][j] = 0.f;

    for (int k0 = 0; k0 < K; k0 += BK) {
#pragma unroll
        for (int i = tid; i < BM * BK; i += 256) {
            int r = i >> 3, c = i & 7;
            int gr = bm + r;
            As[c][r] = (gr < M) ? A[(size_t)gr * lda + (k0 + c)] : 0.f;
        }
#pragma unroll
        for (int i = tid; i < BK * BN; i += 256) {
            int r = i / BN, c = i % BN;
            Bs[r][c] = W[(size_t)(k0 + r) * NC + (bn + c)];
        }
        __syncthreads();
#pragma unroll
        for (int k = 0; k < BK; k++) {
            float a[TM], b[TN];
#pragma unroll
            for (int i = 0; i < TM; i++) a[i] = As[k][tr * TM + i];
#pragma unroll
            for (int j = 0; j < TN; j++) b[j] = Bs[k][tc * TN + j];
#pragma unroll
            for (int i = 0; i < TM; i++)
#pragma unroll
                for (int j = 0; j < TN; j++) acc[i][j] += a[i] * b[j];
        }
        __syncthreads();
    }
#pragma unroll
    for (int i = 0; i < TM; i++) {
        int gr = bm + tr * TM + i;
        if (gr >= M) continue;
#pragma unroll
        for (int j = 0; j < TN; j++) {
            int gc = bn + tc * TN + j;
            float v = acc[i][j];
            if (bias) v += bias[gc];
            if (act) v = fmaxf(v, 0.f);
            C[(size_t)gr * ldc + gc] = v;
        }
    }
}

// pack gated [wl | wr] into g_Wp [nb*64, 128]
__global__ void pack_kernel(const float* __restrict__ wl, const float* __restrict__ wr,
                            const float* __restrict__ skip, int layer, int nb) {
    int idx = blockIdx.x * blockDim.x + threadIdx.x;
    int total = nb * 64 * 128;
    if (idx >= total) return;
    int k = idx >> 7, c = idx & 127;
    float g = 1.f / (1.f + __expf(-skip[layer * 3 + (k >> 6)]));
    float w = (c < 64) ? wl[k * 64 + c] : wr[k * 64 + (c - 64)];
    g_Wp[idx] = g * w;
}

// one warp per node: sum y[src] over CSR row, h = relu(sum*invdeg + bl + r)
__global__ void agg_kernel(const float* __restrict__ bl, int outcol) {
    int gw = (blockIdx.x * blockDim.x + threadIdx.x) >> 5;
    int lane = threadIdx.x & 31;
    if (gw >= NN) return;
    int n = gw;
    int beg = g_rowptr[n], cnt = g_cnt[n];
    float sx = 0.f, sy = 0.f;
    for (int k = 0; k < cnt; k++) {
        int src = g_csr_src[beg + k];
        float2 v = *reinterpret_cast<const float2*>(&g_yr[(size_t)src * 128 + 2 * lane]);
        sx += v.x;
        sy += v.y;
    }
    float inv = g_invdeg[n];
    float2 r = *reinterpret_cast<const float2*>(&g_yr[(size_t)n * 128 + 64 + 2 * lane]);
    float h0 = fmaxf(sx * inv + bl[2 * lane] + r.x, 0.f);
    float h1 = fmaxf(sy * inv + bl[2 * lane + 1] + r.y, 0.f);
    g_emb[(size_t)n * 256 + outcol + 2 * lane] = h0;
    g_emb[(size_t)n * 256 + outcol + 2 * lane + 1] = h1;
}

// column sum of g_emb -> g_s[256]
__global__ void colsum_kernel() {
    int c = threadIdx.x;  // 256 threads
    int per = (NN + gridDim.x - 1) / gridDim.x;
    int n0 = blockIdx.x * per;
    int n1 = n0 + per;
    if (n1 > NN) n1 = NN;
    float s = 0.f;
    for (int n = n0; n < n1; n++) s += g_emb[(size_t)n * 256 + c];
    atomicAdd(&g_s[c], s);
}

// tiny post-mlp on s[256] -> out[64]
__global__ void post_kernel(const float* __restrict__ w1, const float* __restrict__ b1,
                            const float* __restrict__ w2, const float* __restrict__ b2,
                            const float* __restrict__ w3, const float* __restrict__ b3,
                            const float* __restrict__ w4, const float* __restrict__ b4,
                            float* __restrict__ out) {
    __shared__ float s1[64], s2[64], s3[256];
    int t = threadIdx.x;
    if (t < 64) {
        float a = b1[t];
        for (int k = 0; k < 256; k++) a += g_s[k] * w1[k * 64 + t];
        s1[t] = (a > 0.f) ? a : 0.1f * a;  // leaky relu 0.1
    }
    __syncthreads();
    if (t < 64) {
        float a = b2[t];
        for (int k = 0; k < 64; k++) a += s1[k] * w2[k * 64 + t];
        s2[t] = fmaxf(a, 0.f);
    }
    __syncthreads();
    {
        float a = b3[t];
        for (int k = 0; k < 64; k++) a += s2[k] * w3[k * 256 + t];
        s3[t] = fmaxf(a, 0.f);
    }
    __syncthreads();
    if (t < 64) {
        float a = b4[t];
        for (int k = 0; k < 256; k++) a += s3[k] * w4[k * 64 + t];  // FIXED: row stride 64
        out[t] = a;
    }
}

// ---------------- launch ----------------
extern "C" void kernel_launch(void* const* d_in, const int* in_sizes, int n_in,
                              void* d_out, int out_size) {
    const float* node_features = (const float*)d_in[0];
    const int*   edge_index    = (const int*)d_in[1];
    const float* pre_w1 = (const float*)d_in[2];
    const float* pre_b1 = (const float*)d_in[3];
    const float* pre_w2 = (const float*)d_in[4];
    const float* pre_b2 = (const float*)d_in[5];
    const float* skip   = (const float*)d_in[6];
    const float* wl[3] = {(const float*)d_in[7], (const float*)d_in[10], (const float*)d_in[13]};
    const float* bl[3] = {(const float*)d_in[8], (const float*)d_in[11], (const float*)d_in[14]};
    const float* wr[3] = {(const float*)d_in[9], (const float*)d_in[12], (const float*)d_in[15]};
    const float* post_w1 = (const float*)d_in[16];
    const float* post_b1 = (const float*)d_in[17];
    const float* post_w2 = (const float*)d_in[18];
    const float* post_b2 = (const float*)d_in[19];
    const float* post_w3 = (const float*)d_in[20];
    const float* post_b3 = (const float*)d_in[21];
    const float* post_w4 = (const float*)d_in[22];
    const float* post_b4 = (const float*)d_in[23];
    float* out = (float*)d_out;

    float *p_t, *p_emb, *p_yr, *p_Wp;
    cudaGetSymbolAddress((void**)&p_t, g_t);
    cudaGetSymbolAddress((void**)&p_emb, g_emb);
    cudaGetSymbolAddress((void**)&p_yr, g_yr);
    cudaGetSymbolAddress((void**)&p_Wp, g_Wp);

    // graph structure (rebuilt each launch; deterministic work)
    zero_kernel<<<(NN + 255) / 256, 256>>>();
    hist_kernel<<<(EE + 255) / 256, 256>>>(edge_index);
    scan_kernel<<<1, 1024>>>();
    scatter_kernel<<<(EE + 255) / 256, 256>>>(edge_index);

    const int MB = (NN + 127) / 128;  // 391

    // pre-mlp: t = relu(X @ pre_w1 + b1); emb[:,0:64] = t @ pre_w2 + b2
    sgemm_kernel<64><<<dim3(1, MB), 256>>>(node_features, 128, 128, pre_w1, 64, p_t, 64, NN,
                                           pre_b1, 1);
    sgemm_kernel<64><<<dim3(1, MB), 256>>>(p_t, 64, 64, pre_w2, 64, p_emb, 256, NN,
                                           pre_b2, 0);

    for (int layer = 0; layer < 3; layer++) {
        int nb = layer + 1;
        int K = 64 * nb;
        pack_kernel<<<(nb * 64 * 128 + 255) / 256, 256>>>(wl[layer], wr[layer], skip, layer, nb);
        sgemm_kernel<128><<<dim3(1, MB), 256>>>(p_emb, 256, K, p_Wp, 128, p_yr, 128, NN,
                                                (const float*)nullptr, 0);
        agg_kernel<<<(NN * 32 + 255) / 256, 256>>>(bl[layer], 64 * (layer + 1));
    }

    colsum_kernel<<<256, 256>>>();
    post_kernel<<<1, 256>>>(post_w1, post_b1, post_w2, post_b2, post_w3, post_b3,
                            post_w4, post_b4, out);
}

// round 4
// speedup vs baseline: 1.5362x; 1.5362x over previous
#include <cuda_runtime.h>
#include <cuda_bf16.h>
#include <math.h>
#include <stdint.h>

#define NN 50000
#define EE 800000

// ================= scratch (device globals) =================
__device__ float g_emb[(size_t)NN * 256];   // [x | h1 | h2 | h3]
__device__ float g_t[(size_t)NN * 64];      // pre-mlp intermediate
__device__ float g_yr[(size_t)NN * 128];    // per-layer [y | r]
__device__ unsigned short g_Bh[192 * 128];  // B hi, mma-fragment order
__device__ unsigned short g_Bl[192 * 128];  // B lo, mma-fragment order
__device__ int   g_cnt[NN];
__device__ int   g_rowptr[NN];
__device__ int   g_cursor[NN];
__device__ int   g_csr_src[EE];
__device__ float g_invdeg[NN];
__device__ float g_s[256];

// ================= setup =================
__global__ void zero_kernel() {
    int i = blockIdx.x * blockDim.x + threadIdx.x;
    if (i < NN) g_cnt[i] = 0;
    if (i < 256) g_s[i] = 0.f;
}
__global__ void hist_kernel(const int* __restrict__ ei) {
    int e = blockIdx.x * blockDim.x + threadIdx.x;
    if (e < EE) atomicAdd(&g_cnt[ei[EE + e]], 1);
}
__global__ void scan_kernel() {
    __shared__ int partial[1024];
    const int CH = (NN + 1023) / 1024;
    int tid = threadIdx.x;
    int start = tid * CH;
    int sum = 0;
    for (int i = 0; i < CH; i++) { int idx = start + i; if (idx < NN) sum += g_cnt[idx]; }
    partial[tid] = sum;
    __syncthreads();
    for (int off = 1; off < 1024; off <<= 1) {
        int add = (tid >= off) ? partial[tid - off] : 0;
        __syncthreads();
        partial[tid] += add;
        __syncthreads();
    }
    int base = (tid == 0) ? 0 : partial[tid - 1];
    for (int i = 0; i < CH; i++) {
        int idx = start + i;
        if (idx < NN) {
            int c = g_cnt[idx];
            g_rowptr[idx] = base;
            g_cursor[idx] = base;
            g_invdeg[idx] = 1.0f / (float)(c > 1 ? c : 1);
            base += c;
        }
    }
}
__global__ void scatter_kernel(const int* __restrict__ ei) {
    int e = blockIdx.x * blockDim.x + threadIdx.x;
    if (e < EE) {
        int dst = ei[EE + e];
        int pos = atomicAdd(&g_cursor[dst], 1);
        g_csr_src[pos] = ei[e];
    }
}

// ================= pack B into m16n8k16 fragment order (hi/lo bf16) =================
// Logical B is [K, NTILE] (k-major). Fragment (kc, nc): lane t holds
//   b_reg0 halves = B[kc*16 + 2*(t%4) + {0,1}, nc*8 + t/4]
//   b_reg1 halves = same rows + 8.
// u32 index = ((kc*(NTILE/8) + nc)*32 + lane)*2 + reg; halfword = k&1.
__global__ void packB_kernel(const float* __restrict__ wl, const float* __restrict__ wr,
                             const float* __restrict__ skip, int layer, int K, int NTILE) {
    int idx = blockIdx.x * blockDim.x + threadIdx.x;
    if (idx >= K * NTILE) return;
    int k = idx / NTILE, n = idx - k * NTILE;
    float w;
    if (wr) {
        float g = 1.f / (1.f + expf(-skip[layer * 3 + (k >> 6)]));
        w = ((n < 64) ? wl[k * 64 + n] : wr[k * 64 + (n - 64)]) * g;
    } else {
        w = wl[k * NTILE + n];
    }
    int kc = k >> 4, kin = k & 15, nc = n >> 3, nin = n & 7;
    int lane = nin * 4 + ((kin & 7) >> 1);
    int reg = kin >> 3, half = kin & 1;
    int hidx = (((kc * (NTILE >> 3) + nc) * 32 + lane) * 2 + reg) * 2 + half;
    __nv_bfloat16 hi = __float2bfloat16(w);
    __nv_bfloat16 lo = __float2bfloat16(w - __bfloat162float(hi));
    g_Bh[hidx] = __bfloat16_as_ushort(hi);
    g_Bl[hidx] = __bfloat16_as_ushort(lo);
}

// ================= HMMA GEMM: C[M,NTILE] = act(A[M,K] @ B + bias) =================
__device__ __forceinline__ void mma16816(float* acc, const uint32_t* a,
                                         uint32_t b0, uint32_t b1) {
    asm volatile(
        "mma.sync.aligned.m16n8k16.row.col.f32.bf16.bf16.f32 "
        "{%0,%1,%2,%3}, {%4,%5,%6,%7}, {%8,%9}, {%0,%1,%2,%3};"
        : "+f"(acc[0]), "+f"(acc[1]), "+f"(acc[2]), "+f"(acc[3])
        : "r"(a[0]), "r"(a[1]), "r"(a[2]), "r"(a[3]), "r"(b0), "r"(b1));
}
__device__ __forceinline__ void split2(float x, float y, uint32_t& hi, uint32_t& lo) {
    __nv_bfloat16 hx = __float2bfloat16(x), hy = __float2bfloat16(y);
    __nv_bfloat16 lx = __float2bfloat16(x - __bfloat162float(hx));
    __nv_bfloat16 ly = __float2bfloat16(y - __bfloat162float(hy));
    hi = ((uint32_t)__bfloat16_as_ushort(hy) << 16) | __bfloat16_as_ushort(hx);
    lo = ((uint32_t)__bfloat16_as_ushort(ly) << 16) | __bfloat16_as_ushort(lx);
}

template <int NTILE>
__global__ void __launch_bounds__(256) mma_gemm_kernel(
    const float* __restrict__ A, int lda, int K,
    const float* __restrict__ bias, int act,
    float* __restrict__ C, int ldc, int M) {
    constexpr int NFRAG = NTILE / 8;
    const int tid = threadIdx.x;
    const int wid = tid >> 5, lane = tid & 31;
    const int q = lane & 3, tq = lane >> 2;
    const int r0 = blockIdx.x * 128 + wid * 16 + tq;
    const int r1 = r0 + 8;

    float acc[NFRAG][4];
#pragma unroll
    for (int i = 0; i < NFRAG; i++)
#pragma unroll
        for (int j = 0; j < 4; j++) acc[i][j] = 0.f;

    const uint32_t* __restrict__ Bh = (const uint32_t*)g_Bh;
    const uint32_t* __restrict__ Bl = (const uint32_t*)g_Bl;

    for (int kc = 0; kc < K / 16; kc++) {
        const int c0 = kc * 16 + 2 * q;
        float2 v00 = make_float2(0.f, 0.f), v10 = v00, v01 = v00, v11 = v00;
        if (r0 < M) {
            v00 = *(const float2*)&A[(size_t)r0 * lda + c0];
            v01 = *(const float2*)&A[(size_t)r0 * lda + c0 + 8];
        }
        if (r1 < M) {
            v10 = *(const float2*)&A[(size_t)r1 * lda + c0];
            v11 = *(const float2*)&A[(size_t)r1 * lda + c0 + 8];
        }
        uint32_t ah[4], al[4];
        split2(v00.x, v00.y, ah[0], al[0]);
        split2(v10.x, v10.y, ah[1], al[1]);
        split2(v01.x, v01.y, ah[2], al[2]);
        split2(v11.x, v11.y, ah[3], al[3]);

        const int base = kc * NFRAG * 64 + lane * 2;
#pragma unroll
        for (int nc = 0; nc < NFRAG; nc++) {
            int bi = base + nc * 64;
            uint32_t bh0 = Bh[bi], bh1 = Bh[bi + 1];
            uint32_t bl0 = Bl[bi], bl1 = Bl[bi + 1];
            mma16816(acc[nc], ah, bh0, bh1);
            mma16816(acc[nc], ah, bl0, bl1);
            mma16816(acc[nc], al, bh0, bh1);
        }
    }

#pragma unroll
    for (int nc = 0; nc < NFRAG; nc++) {
        int col = nc * 8 + 2 * q;
        float b0v = bias ? bias[col] : 0.f;
        float b1v = bias ? bias[col + 1] : 0.f;
        if (r0 < M) {
            float x = acc[nc][0] + b0v, y = acc[nc][1] + b1v;
            if (act) { x = fmaxf(x, 0.f); y = fmaxf(y, 0.f); }
            *(float2*)&C[(size_t)r0 * ldc + col] = make_float2(x, y);
        }
        if (r1 < M) {
            float x = acc[nc][2] + b0v, y = acc[nc][3] + b1v;
            if (act) { x = fmaxf(x, 0.f); y = fmaxf(y, 0.f); }
            *(float2*)&C[(size_t)r1 * ldc + col] = make_float2(x, y);
        }
    }
}

// ================= aggregation: one warp per node =================
__global__ void agg_kernel(const float* __restrict__ bl, int outcol) {
    int gw = (blockIdx.x * blockDim.x + threadIdx.x) >> 5;
    int lane = threadIdx.x & 31;
    if (gw >= NN) return;
    int n = gw;
    int beg = g_rowptr[n], cnt = g_cnt[n];
    float sx = 0.f, sy = 0.f;
    for (int k = 0; k < cnt; k++) {
        int src = g_csr_src[beg + k];
        float2 v = *reinterpret_cast<const float2*>(&g_yr[(size_t)src * 128 + 2 * lane]);
        sx += v.x;
        sy += v.y;
    }
    float inv = g_invdeg[n];
    float2 r = *reinterpret_cast<const float2*>(&g_yr[(size_t)n * 128 + 64 + 2 * lane]);
    float h0 = fmaxf(sx * inv + bl[2 * lane] + r.x, 0.f);
    float h1 = fmaxf(sy * inv + bl[2 * lane + 1] + r.y, 0.f);
    g_emb[(size_t)n * 256 + outcol + 2 * lane] = h0;
    g_emb[(size_t)n * 256 + outcol + 2 * lane + 1] = h1;
}

// ================= column sum + post mlp =================
__global__ void colsum_kernel() {
    int c = threadIdx.x;
    int per = (NN + gridDim.x - 1) / gridDim.x;
    int n0 = blockIdx.x * per;
    int n1 = n0 + per;
    if (n1 > NN) n1 = NN;
    float s = 0.f;
    for (int n = n0; n < n1; n++) s += g_emb[(size_t)n * 256 + c];
    atomicAdd(&g_s[c], s);
}
__global__ void post_kernel(const float* __restrict__ w1, const float* __restrict__ b1,
                            const float* __restrict__ w2, const float* __restrict__ b2,
                            const float* __restrict__ w3, const float* __restrict__ b3,
                            const float* __restrict__ w4, const float* __restrict__ b4,
                            float* __restrict__ out) {
    __shared__ float s1[64], s2[64], s3[256];
    int t = threadIdx.x;
    if (t < 64) {
        float a = b1[t];
        for (int k = 0; k < 256; k++) a += g_s[k] * w1[k * 64 + t];
        s1[t] = (a > 0.f) ? a : 0.1f * a;
    }
    __syncthreads();
    if (t < 64) {
        float a = b2[t];
        for (int k = 0; k < 64; k++) a += s1[k] * w2[k * 64 + t];
        s2[t] = fmaxf(a, 0.f);
    }
    __syncthreads();
    {
        float a = b3[t];
        for (int k = 0; k < 64; k++) a += s2[k] * w3[k * 256 + t];
        s3[t] = fmaxf(a, 0.f);
    }
    __syncthreads();
    if (t < 64) {
        float a = b4[t];
        for (int k = 0; k < 256; k++) a += s3[k] * w4[k * 64 + t];
        out[t] = a;
    }
}

// ================= launch =================
extern "C" void kernel_launch(void* const* d_in, const int* in_sizes, int n_in,
                              void* d_out, int out_size) {
    const float* node_features = (const float*)d_in[0];
    const int*   edge_index    = (const int*)d_in[1];
    const float* pre_w1 = (const float*)d_in[2];
    const float* pre_b1 = (const float*)d_in[3];
    const float* pre_w2 = (const float*)d_in[4];
    const float* pre_b2 = (const float*)d_in[5];
    const float* skip   = (const float*)d_in[6];
    const float* wl[3] = {(const float*)d_in[7], (const float*)d_in[10], (const float*)d_in[13]};
    const float* bl[3] = {(const float*)d_in[8], (const float*)d_in[11], (const float*)d_in[14]};
    const float* wr[3] = {(const float*)d_in[9], (const float*)d_in[12], (const float*)d_in[15]};
    const float* post_w1 = (const float*)d_in[16];
    const float* post_b1 = (const float*)d_in[17];
    const float* post_w2 = (const float*)d_in[18];
    const float* post_b2 = (const float*)d_in[19];
    const float* post_w3 = (const float*)d_in[20];
    const float* post_b3 = (const float*)d_in[21];
    const float* post_w4 = (const float*)d_in[22];
    const float* post_b4 = (const float*)d_in[23];
    float* out = (float*)d_out;

    float *p_t, *p_emb, *p_yr;
    cudaGetSymbolAddress((void**)&p_t, g_t);
    cudaGetSymbolAddress((void**)&p_emb, g_emb);
    cudaGetSymbolAddress((void**)&p_yr, g_yr);

    // CSR build
    zero_kernel<<<(NN + 255) / 256, 256>>>();
    hist_kernel<<<(EE + 255) / 256, 256>>>(edge_index);
    scan_kernel<<<1, 1024>>>();
    scatter_kernel<<<(EE + 255) / 256, 256>>>(edge_index);

    const int MB = (NN + 127) / 128;  // 391

    // pre-mlp GEMM 1: t = relu(X @ pre_w1 + b1), K=128 N=64
    packB_kernel<<<(128 * 64 + 255) / 256, 256>>>(pre_w1, nullptr, nullptr, 0, 128, 64);
    mma_gemm_kernel<64><<<MB, 256>>>(node_features, 128, 128, pre_b1, 1, p_t, 64, NN);
    // pre-mlp GEMM 2: emb[:,0:64] = t @ pre_w2 + b2, K=64 N=64
    packB_kernel<<<(64 * 64 + 255) / 256, 256>>>(pre_w2, nullptr, nullptr, 0, 64, 64);
    mma_gemm_kernel<64><<<MB, 256>>>(p_t, 64, 64, pre_b2, 0, p_emb, 256, NN);

    for (int layer = 0; layer < 3; layer++) {
        int K = 64 * (layer + 1);
        packB_kernel<<<(K * 128 + 255) / 256, 256>>>(wl[layer], wr[layer], skip, layer, K, 128);
        mma_gemm_kernel<128><<<MB, 256>>>(p_emb, 256, K, (const float*)nullptr, 0, p_yr, 128, NN);
        agg_kernel<<<(NN * 32 + 255) / 256, 256>>>(bl[layer], 64 * (layer + 1));
    }

    colsum_kernel<<<256, 256>>>();
    post_kernel<<<1, 256>>>(post_w1, post_b1, post_w2, post_b2, post_w3, post_b3,
                            post_w4, post_b4, out);
}